// round 13
// baseline (speedup 1.0000x reference)
#include <cuda_runtime.h>
#include <cuda_fp16.h>
#include <math.h>
#include <stdint.h>

#define T_TYPES 2
#define B_SZ 16
#define L_SZ 2048
#define N_EV 4096          // T*L
#define D_EMBD 512
#define G_SZ 1024
#define NPAIR 256          // D/2
#define TAB_N 4096         // symmetric table, u in [0,1024], h = 1/4
#define INV_SQRT_D 0.04419417382415922f
#define LOG2_1E4_OVER_256 0.051905126482615036f   // log2(10000)/256

// ---------------- device scratch ----------------
__device__ float  g_omf[NPAIR];
__device__ float2 g_tabf[TAB_N + 1];                 // fp32 master: (H, H'*h) * 0.5
__device__ float  g_ec[T_TYPES * G_SZ];              // exp(type_emb . q[g] / sqrt(D))
__device__ float  g_sc[B_SZ * G_SZ];                 // 1 / sum(stored w)
__device__ __align__(128) __half g_w[(size_t)B_SZ * G_SZ * N_EV];   // 128MB
__device__ __align__(128) __half g_e[(size_t)B_SZ * D_EMBD * N_EV]; // 64MB

// ---------------- helpers ----------------
__device__ __forceinline__ uint32_t smem_u32(const void* p) {
    uint32_t a;
    asm("{ .reg .u64 t; cvta.to.shared.u64 t, %1; cvt.u32.u64 %0, t; }" : "=r"(a) : "l"(p));
    return a;
}
__device__ __forceinline__ void cp16(uint32_t dst, const void* src) {
    asm volatile("cp.async.cg.shared.global [%0], [%1], 16;" :: "r"(dst), "l"(src));
}
__device__ __forceinline__ void ldm_x4(uint32_t (&r)[4], uint32_t addr) {
    asm volatile("ldmatrix.sync.aligned.m8n8.x4.shared.b16 {%0,%1,%2,%3}, [%4];"
                 : "=r"(r[0]), "=r"(r[1]), "=r"(r[2]), "=r"(r[3]) : "r"(addr));
}
__device__ __forceinline__ void mma16816(float (&c)[4], const uint32_t (&a)[4],
                                         uint32_t b0, uint32_t b1) {
    asm volatile("mma.sync.aligned.m16n8k16.row.col.f32.f16.f16.f32 "
                 "{%0,%1,%2,%3}, {%4,%5,%6,%7}, {%8,%9}, {%0,%1,%2,%3};"
                 : "+f"(c[0]), "+f"(c[1]), "+f"(c[2]), "+f"(c[3])
                 : "r"(a[0]), "r"(a[1]), "r"(a[2]), "r"(a[3]), "r"(b0), "r"(b1));
}
// fp32 Cody-Waite range reduction: x in [0, 1024], |r| <= pi
__device__ __forceinline__ float reduce_f32(float x) {
    const float INV2PI = 0.15915494309189535f;
    const float C1 = 6.28125f;
    const float C2 = 1.9353071795864769e-3f;
    float kf = rintf(x * INV2PI);
    float r = fmaf(-kf, C1, x);
    return fmaf(-kf, C2, r);
}

// ---------------- setup: table (fp32 master) + ec, one launch ----------------
// blocks [0,513): warp per table entry j; blocks [513,769): warp per (t,g)
__global__ void k_setup(const float* __restrict__ type_emb) {
    int lane = threadIdx.x & 31;
    if (blockIdx.x < 513) {
        if (blockIdx.x == 0 && threadIdx.x < NPAIR)
            g_omf[threadIdx.x] = exp2f(-(float)threadIdx.x * LOG2_1E4_OVER_256);
        int j = (blockIdx.x * blockDim.x + threadIdx.x) >> 5;
        if (j > TAB_N) return;
        float u = (float)j * 0.25f;
        float rc = 0.f, rs = 0.f;
        #pragma unroll
        for (int q = 0; q < 8; q++) {
            int i = lane + q * 32;
            float om = exp2f(-(float)i * LOG2_1E4_OVER_256);
            float r = reduce_f32(u * om);
            float s, c; __sincosf(r, &s, &c);
            rc += c;
            rs += om * s;
        }
        #pragma unroll
        for (int off = 16; off; off >>= 1) {
            rc += __shfl_xor_sync(0xffffffffu, rc, off);
            rs += __shfl_xor_sync(0xffffffffu, rs, off);
        }
        if (lane == 0) {
            float H   = expf(rc * INV_SQRT_D) * 0.5f;            // prescale 1/2
            float Hdh = -H * rs * INV_SQRT_D * 0.25f;            // (H/2)' * h
            g_tabf[j] = make_float2(H, Hdh);
        }
    } else {
        int e = (((int)blockIdx.x - 513) * 256 + threadIdx.x) >> 5;   // 0..2047
        int t = e >> 10, g = e & 1023;
        float mg = (float)g + 0.5f;
        float acc = 0.f;
        #pragma unroll
        for (int q = 0; q < 8; q++) {
            int i = lane + q * 32;
            float om = exp2f(-(float)i * LOG2_1E4_OVER_256);
            float r = reduce_f32(mg * om);
            float s, c; __sincosf(r, &s, &c);
            acc += type_emb[t * D_EMBD + 2 * i] * s + type_emb[t * D_EMBD + 2 * i + 1] * c;
        }
        #pragma unroll
        for (int off = 16; off; off >>= 1) acc += __shfl_xor_sync(0xffffffffu, acc, off);
        if (lane == 0) g_ec[t * G_SZ + g] = expf(acc * INV_SQRT_D);
    }
}

// unnormalized (half-scaled) weight: pre-baked cubic coeffs, 3-FMA Horner
__device__ __forceinline__ float w_rawh(const uint2* tab, float tm, float mg, float ec) {
    float u  = fabsf(tm - mg);
    float x  = u * 4.f;
    float xf = floorf(x);
    int idx  = (int)xf;
    float fr = x - xf;
    uint2 T = tab[idx];
    float2 a = __half22float2(*(__half2*)&T.x);    // (c0, c1)
    float2 b = __half22float2(*(__half2*)&T.y);    // (c2, c3)
    float p  = fmaf(fr, fmaf(fr, fmaf(fr, b.y, b.x), a.y), a.x);
    return (tm != 0.f) ? p * ec : 0.5f;            // 0.5 = half-scaled exp(0)
}

// fused: even blocks -> softmax weights (bakes coeffs from fp32 master);
//        odd blocks  -> emb transpose
__global__ void __launch_bounds__(512) k_prep(const float* __restrict__ times,
                                              const float* __restrict__ type_emb,
                                              const int* __restrict__ real_len) {
    int tid = threadIdx.x;                          // 512
    if (blockIdx.x & 1) {
        // ---------------- emb: [b][d][n] fp16, 64 n per block ----------------
        int idx = (int)blockIdx.x >> 1;             // 0..1023
        int b = idx >> 6;
        int n0 = (idx & 63) * 64;
        int tIdx = n0 >> 11;
        int rl = real_len[tIdx * B_SZ + b];
        int K = (rl + 63) & ~63;
        if ((n0 & 2047) >= K) return;
        int lane = tid & 31;
        int half = (tid >> 5) & 1;                  // which 32-of-64
        int wslot = tid >> 6;                       // 0..7
        int n = n0 + half * 32 + lane;
        float tm = times[(size_t)tIdx * (B_SZ * L_SZ) + (size_t)b * L_SZ + (n & 2047)];
        bool nz = (tm != 0.f);
        uint32_t base = (uint32_t)b * (D_EMBD * N_EV) + n;
        #pragma unroll 4
        for (int ii = 0; ii < 32; ii++) {
            int i = wslot + ii * 8;                 // pair index 0..255
            float x = tm * g_omf[i];
            float r = reduce_f32(x);
            float s, c; __sincosf(r, &s, &c);
            float2 te = *(const float2*)&type_emb[tIdx * D_EMBD + 2 * i];
            __half h0 = __float2half_rn(nz ? s + te.x : 0.f);
            __half h1 = __float2half_rn(nz ? c + te.y : 0.f);
            g_e[base + (uint32_t)(2 * i) * N_EV]     = h0;
            g_e[base + (uint32_t)(2 * i + 1) * N_EV] = h1;
        }
        return;
    }
    // ---------------- weights over valid ranges only ----------------
    extern __shared__ float smW[];
    uint2* tab = (uint2*)smW;                       // TAB_N uint2 (32KB)
    float* ts  = smW + 2 * TAB_N;                   // N_EV floats (16KB)
    int bx = (int)blockIdx.x >> 1;                  // 0..1023
    int b = bx >> 6;
    int gx = bx & 63;
    int rl0 = real_len[b], rl1 = real_len[B_SZ + b];
    int K0 = (rl0 + 63) & ~63, K1 = (rl1 + 63) & ~63;
    // bake half4 cubic coefficients from the fp32 master while staging
    for (int j = tid; j < TAB_N; j += 512) {
        float2 a = g_tabf[j];
        float2 c = g_tabf[j + 1];
        float d  = c.x - a.x;
        float c2 = 3.f * d - 2.f * a.y - c.y;
        float c3 = a.y + c.y - 2.f * d;
        __half2 lo = __floats2half2_rn(a.x, a.y);
        __half2 hi = __floats2half2_rn(c2, c3);
        tab[j] = make_uint2(*(uint32_t*)&lo, *(uint32_t*)&hi);
    }
    for (int j = tid; j < K0; j += 512)
        ts[j] = times[(size_t)b * L_SZ + j];
    for (int j = tid; j < K1; j += 512)
        ts[2048 + j] = times[(size_t)(B_SZ * L_SZ) + (size_t)b * L_SZ + j];
    __syncthreads();
    int warp = tid >> 5, lane = tid & 31;
    int g = gx * 16 + warp;
    float ec0 = g_ec[g], ec1 = g_ec[G_SZ + g];
    float mg = (float)g + 0.5f;
    uint32_t base = ((uint32_t)(b * G_SZ + g)) << 12;

    // pass A: min distance among valid nonzero events (registers only)
    float umin0 = 1e9f, umin1 = 1e9f;
    for (int n0 = lane * 4; n0 < K0; n0 += 128) {
        float4 t4 = *(const float4*)&ts[n0];
        #pragma unroll
        for (int q = 0; q < 4; q++) {
            float tm = (q == 0) ? t4.x : (q == 1) ? t4.y : (q == 2) ? t4.z : t4.w;
            bool valid = (n0 + q < rl0) && (tm != 0.f);
            umin0 = fminf(umin0, valid ? fabsf(tm - mg) : 1e9f);
        }
    }
    for (int n0 = lane * 4; n0 < K1; n0 += 128) {
        float4 t4 = *(const float4*)&ts[2048 + n0];
        #pragma unroll
        for (int q = 0; q < 4; q++) {
            float tm = (q == 0) ? t4.x : (q == 1) ? t4.y : (q == 2) ? t4.z : t4.w;
            bool valid = (n0 + q < rl1) && (tm != 0.f);
            umin1 = fminf(umin1, valid ? fabsf(tm - mg) : 1e9f);
        }
    }
    #pragma unroll
    for (int off = 16; off; off >>= 1) {
        umin0 = fminf(umin0, __shfl_xor_sync(0xffffffffu, umin0, off));
        umin1 = fminf(umin1, __shfl_xor_sync(0xffffffffu, umin1, off));
    }
    float b0 = w_rawh(tab, mg + fminf(umin0, 1023.5f), mg, ec0);
    float b1 = w_rawh(tab, mg + fminf(umin1, 1023.5f), mg, ec1);
    float bound = fmaxf(fmaxf(b0, b1), 0.5f);
    float invb = 1.0f / bound;

    // pass B: interp + quantize + fp32 sum of quantized values
    float sum = 0.f;
    #pragma unroll 1
    for (int seg = 0; seg < 2; seg++) {
        int K  = seg ? K1 : K0;
        int rl = seg ? rl1 : rl0;
        float ec = seg ? ec1 : ec0;
        int off_ts = seg ? 2048 : 0;
        for (int n0 = lane * 4; n0 < K; n0 += 128) {
            float4 t4 = *(const float4*)&ts[off_ts + n0];
            float w[4];
            #pragma unroll
            for (int q = 0; q < 4; q++) {
                float tm = (q == 0) ? t4.x : (q == 1) ? t4.y : (q == 2) ? t4.z : t4.w;
                float wr = w_rawh(tab, tm, mg, ec);
                w[q] = (n0 + q < rl) ? wr * invb : 0.f;
            }
            __half2 p0 = __floats2half2_rn(w[0], w[1]);
            __half2 p1 = __floats2half2_rn(w[2], w[3]);
            float2 f0 = __half22float2(p0);
            float2 f1 = __half22float2(p1);
            sum += (f0.x + f0.y) + (f1.x + f1.y);
            uint2 pk = make_uint2(*(uint32_t*)&p0, *(uint32_t*)&p1);
            *(uint2*)&g_w[base + off_ts + n0] = pk;
        }
    }
    #pragma unroll
    for (int off = 16; off; off >>= 1) sum += __shfl_xor_sync(0xffffffffu, sum, off);
    if (lane == 0) g_sc[b * G_SZ + g] = 1.0f / sum;
}

// ---------------- fp16 mma.sync GEMM: ragged K, 128x128 tiles ----------------
#define KT 64
#define STAGES 3
#define A_TILE_B (128 * 128)           // 16384 (128 rows x 128B)
#define STG_B (2 * A_TILE_B)           // 32768

__global__ void __launch_bounds__(256, 2) k_gemm(const int* __restrict__ real_len,
                                                 float* __restrict__ out) {
    extern __shared__ char smG[];
    uint32_t smb = smem_u32(smG);
    float* smInv = (float*)(smG + STAGES * STG_B);
    int tid = threadIdx.x, wid = tid >> 5, lane = tid & 31;
    int b  = blockIdx.x;                      // b fastest -> waves mix all b's
    int g0 = (blockIdx.y & 7) * 128;
    int d0 = (blockIdx.y >> 3) * 128;
    int wm = wid >> 2, wn = wid & 3;          // 2 x 4 warps; warp tile 64g x 32d

    int nk0 = (((real_len[b] + 63) & ~63) >> 6);
    int nk1 = (((real_len[B_SZ + b] + 63) & ~63) >> 6);
    int nk  = nk0 + nk1;                      // 2..64

    if (tid < 128) smInv[tid] = g_sc[b * G_SZ + g0 + tid];

    const __half* wbase = g_w + (((uint32_t)(b * G_SZ + g0)) << 12);
    const __half* ebase = g_e + (((uint32_t)(b * D_EMBD + d0)) << 12);

    auto kof = [&](int i) { return i < nk0 ? i * KT : (i - nk0) * KT + 2048; };

    auto load_stage = [&](int s, int k0) {
        uint32_t st = smb + s * STG_B;
        #pragma unroll
        for (int t = 0; t < 4; t++) {           // A: 128 rows x 8 chunks
            int id = tid + t * 256;
            int row = id >> 3, c = id & 7;
            uint32_t col = (uint32_t)(c * 16) ^ (uint32_t)((row & 7) << 4);
            cp16(st + row * 128 + col, wbase + ((uint32_t)row << 12) + k0 + c * 8);
        }
        #pragma unroll
        for (int t = 0; t < 4; t++) {           // B: 128 rows x 8 chunks
            int id = tid + t * 256;
            int row = id >> 3, c = id & 7;
            uint32_t col = (uint32_t)(c * 16) ^ (uint32_t)((row & 7) << 4);
            cp16(st + A_TILE_B + row * 128 + col, ebase + ((uint32_t)row << 12) + k0 + c * 8);
        }
        asm volatile("cp.async.commit_group;" ::: "memory");
    };

    float acc[4][4][4];
    #pragma unroll
    for (int i = 0; i < 4; i++)
        #pragma unroll
        for (int j = 0; j < 4; j++)
            #pragma unroll
            for (int q = 0; q < 4; q++) acc[i][j][q] = 0.f;

    load_stage(0, kof(0));
    load_stage(1, kof(1));

    int a_row = (lane & 7) + ((lane >> 3) & 1) * 8;
    int a_col = (lane >> 4) * 16;
    int b_grp = lane >> 3;
    int b_row = (b_grp >> 1) * 8 + (lane & 7);
    int b_col = (b_grp & 1) * 16;
    uint32_t lxor = (uint32_t)((lane & 7) << 4);

    for (int i = 0; i < nk; i++) {
        if (i < nk - 1) asm volatile("cp.async.wait_group 1;" ::: "memory");
        else            asm volatile("cp.async.wait_group 0;" ::: "memory");
        __syncthreads();

        // issue next stage's loads BEFORE compute (buffer freed at iter i-1)
        if (i + 2 < nk) load_stage((i + 2) % 3, kof(i + 2));

        int s = i % 3;
        uint32_t abase = smb + s * STG_B;
        uint32_t bbase = abase + A_TILE_B;
        #pragma unroll
        for (int ks = 0; ks < 4; ks++) {
            uint32_t acol = ((uint32_t)(ks * 32 + a_col)) ^ lxor;
            uint32_t bcol = ((uint32_t)(ks * 32 + b_col)) ^ lxor;
            uint32_t af[4][4], bf[2][4];
            #pragma unroll
            for (int m = 0; m < 4; m++)
                ldm_x4(af[m], abase + (wm * 64 + m * 16 + a_row) * 128 + acol);
            #pragma unroll
            for (int jp = 0; jp < 2; jp++)
                ldm_x4(bf[jp], bbase + (wn * 32 + jp * 16 + b_row) * 128 + bcol);
            #pragma unroll
            for (int m = 0; m < 4; m++)
                #pragma unroll
                for (int j = 0; j < 4; j++)
                    mma16816(acc[m][j], af[m], bf[j >> 1][(j & 1) * 2], bf[j >> 1][(j & 1) * 2 + 1]);
        }
    }

    #pragma unroll
    for (int m = 0; m < 4; m++) {
        int r0 = wm * 64 + m * 16 + (lane >> 2);
        float sc0 = smInv[r0], sc1 = smInv[r0 + 8];
        uint32_t gr0 = (uint32_t)(b * G_SZ + g0 + r0) * D_EMBD + d0 + wn * 32;
        #pragma unroll
        for (int j = 0; j < 4; j++) {
            int col = j * 8 + (lane & 3) * 2;
            *(float2*)(out + gr0 + col) =
                make_float2(acc[m][j][0] * sc0, acc[m][j][1] * sc0);
            *(float2*)(out + gr0 + 8 * D_EMBD + col) =
                make_float2(acc[m][j][2] * sc1, acc[m][j][3] * sc1);
        }
    }
}

// ---------------- launch ----------------
extern "C" void kernel_launch(void* const* d_in, const int* in_sizes, int n_in,
                              void* d_out, int out_size) {
    const float* times    = (const float*)d_in[0];
    const float* type_emb = (const float*)d_in[1];
    const int*   real_len = (const int*)d_in[2];
    float* out = (float*)d_out;
    (void)in_sizes; (void)n_in; (void)out_size;

    size_t smem_w = (size_t)(2 * TAB_N + N_EV) * sizeof(float);              // 48 KB
    size_t smem_g = STAGES * STG_B + 128 * sizeof(float);                    // ~96.5 KB
    cudaFuncSetAttribute(k_prep, cudaFuncAttributeMaxDynamicSharedMemorySize, (int)smem_w);
    cudaFuncSetAttribute(k_gemm, cudaFuncAttributeMaxDynamicSharedMemorySize, (int)smem_g);

    k_setup<<<769, 256>>>(type_emb);
    k_prep<<<2048, 512, smem_w>>>(times, type_emb, real_len);
    k_gemm<<<dim3(B_SZ, (G_SZ / 128) * (D_EMBD / 128)), 256, smem_g>>>(real_len, out);
}

// round 14
// speedup vs baseline: 1.0268x; 1.0268x over previous
#include <cuda_runtime.h>
#include <cuda_fp16.h>
#include <math.h>
#include <stdint.h>

#define T_TYPES 2
#define B_SZ 16
#define L_SZ 2048
#define N_EV 4096          // T*L
#define D_EMBD 512
#define G_SZ 1024
#define NPAIR 256          // D/2
#define TAB_N 4096         // symmetric table, u in [0,1024], h = 1/4
#define INV_SQRT_D 0.04419417382415922f
#define LOG2_1E4_OVER_256 0.051905126482615036f   // log2(10000)/256

// ---------------- device scratch ----------------
__device__ float  g_omf[NPAIR];
__device__ uint2  g_tabh[TAB_N];                     // half4 cubic coeffs (c0,c1,c2,c3)
__device__ float  g_ec[T_TYPES * G_SZ];              // exp(type_emb . q[g] / sqrt(D))
__device__ float  g_sc[B_SZ * G_SZ];                 // 1 / sum(stored w)
__device__ __align__(128) __half g_w[(size_t)B_SZ * G_SZ * N_EV];   // 128MB
__device__ __align__(128) __half g_e[(size_t)B_SZ * D_EMBD * N_EV]; // 64MB

// ---------------- helpers ----------------
__device__ __forceinline__ uint32_t smem_u32(const void* p) {
    uint32_t a;
    asm("{ .reg .u64 t; cvta.to.shared.u64 t, %1; cvt.u32.u64 %0, t; }" : "=r"(a) : "l"(p));
    return a;
}
__device__ __forceinline__ void cp16(uint32_t dst, const void* src) {
    asm volatile("cp.async.cg.shared.global [%0], [%1], 16;" :: "r"(dst), "l"(src));
}
__device__ __forceinline__ void ldm_x4(uint32_t (&r)[4], uint32_t addr) {
    asm volatile("ldmatrix.sync.aligned.m8n8.x4.shared.b16 {%0,%1,%2,%3}, [%4];"
                 : "=r"(r[0]), "=r"(r[1]), "=r"(r[2]), "=r"(r[3]) : "r"(addr));
}
__device__ __forceinline__ void mma16816(float (&c)[4], const uint32_t (&a)[4],
                                         uint32_t b0, uint32_t b1) {
    asm volatile("mma.sync.aligned.m16n8k16.row.col.f32.f16.f16.f32 "
                 "{%0,%1,%2,%3}, {%4,%5,%6,%7}, {%8,%9}, {%0,%1,%2,%3};"
                 : "+f"(c[0]), "+f"(c[1]), "+f"(c[2]), "+f"(c[3])
                 : "r"(a[0]), "r"(a[1]), "r"(a[2]), "r"(a[3]), "r"(b0), "r"(b1));
}
// fp32 Cody-Waite range reduction: x in [0, 1024], |r| <= pi
__device__ __forceinline__ float reduce_f32(float x) {
    const float INV2PI = 0.15915494309189535f;
    const float C1 = 6.28125f;
    const float C2 = 1.9353071795864769e-3f;
    float kf = rintf(x * INV2PI);
    float r = fmaf(-kf, C1, x);
    return fmaf(-kf, C2, r);
}

// ---------------- setup: baked table + ec in ONE launch ----------------
// blocks [0,512): warp per table segment j — computes sums at u_j AND u_{j+1},
//                 emits baked half4 cubic directly.
// blocks [512,768): warp per (t,g) for g_ec.
__global__ void k_setup(const float* __restrict__ type_emb) {
    int lane = threadIdx.x & 31;
    if (blockIdx.x < 512) {
        if (blockIdx.x == 0 && threadIdx.x < NPAIR)
            g_omf[threadIdx.x] = exp2f(-(float)threadIdx.x * LOG2_1E4_OVER_256);
        int j = (blockIdx.x * blockDim.x + threadIdx.x) >> 5;   // 0..4095
        float u0 = (float)j * 0.25f;
        float u1 = u0 + 0.25f;
        float rc0 = 0.f, rs0 = 0.f, rc1 = 0.f, rs1 = 0.f;
        #pragma unroll
        for (int q = 0; q < 8; q++) {
            int i = lane + q * 32;
            float om = exp2f(-(float)i * LOG2_1E4_OVER_256);
            float s, c;
            __sincosf(reduce_f32(u0 * om), &s, &c);
            rc0 += c; rs0 += om * s;
            __sincosf(reduce_f32(u1 * om), &s, &c);
            rc1 += c; rs1 += om * s;
        }
        #pragma unroll
        for (int off = 16; off; off >>= 1) {
            rc0 += __shfl_xor_sync(0xffffffffu, rc0, off);
            rs0 += __shfl_xor_sync(0xffffffffu, rs0, off);
            rc1 += __shfl_xor_sync(0xffffffffu, rc1, off);
            rs1 += __shfl_xor_sync(0xffffffffu, rs1, off);
        }
        if (lane == 0) {
            float H0  = expf(rc0 * INV_SQRT_D) * 0.5f;           // prescale 1/2
            float Hd0 = -H0 * rs0 * INV_SQRT_D * 0.25f;          // (H/2)' * h
            float H1  = expf(rc1 * INV_SQRT_D) * 0.5f;
            float Hd1 = -H1 * rs1 * INV_SQRT_D * 0.25f;
            float d  = H1 - H0;
            float c2 = 3.f * d - 2.f * Hd0 - Hd1;
            float c3 = Hd0 + Hd1 - 2.f * d;
            __half2 lo = __floats2half2_rn(H0, Hd0);
            __half2 hi = __floats2half2_rn(c2, c3);
            g_tabh[j] = make_uint2(*(uint32_t*)&lo, *(uint32_t*)&hi);
        }
    } else {
        int e = (((int)blockIdx.x - 512) * 256 + threadIdx.x) >> 5;   // 0..2047
        int t = e >> 10, g = e & 1023;
        float mg = (float)g + 0.5f;
        float acc = 0.f;
        #pragma unroll
        for (int q = 0; q < 8; q++) {
            int i = lane + q * 32;
            float om = exp2f(-(float)i * LOG2_1E4_OVER_256);
            float r = reduce_f32(mg * om);
            float s, c; __sincosf(r, &s, &c);
            acc += type_emb[t * D_EMBD + 2 * i] * s + type_emb[t * D_EMBD + 2 * i + 1] * c;
        }
        #pragma unroll
        for (int off = 16; off; off >>= 1) acc += __shfl_xor_sync(0xffffffffu, acc, off);
        if (lane == 0) g_ec[t * G_SZ + g] = expf(acc * INV_SQRT_D);
    }
}

// unnormalized (half-scaled) weight: pre-baked cubic coeffs, 3-FMA Horner
__device__ __forceinline__ float w_rawh(const uint2* tab, float tm, float mg, float ec) {
    float u  = fabsf(tm - mg);
    float x  = u * 4.f;
    float xf = floorf(x);
    int idx  = (int)xf;
    float fr = x - xf;
    uint2 T = tab[idx];
    float2 a = __half22float2(*(__half2*)&T.x);    // (c0, c1)
    float2 b = __half22float2(*(__half2*)&T.y);    // (c2, c3)
    float p  = fmaf(fr, fmaf(fr, fmaf(fr, b.y, b.x), a.y), a.x);
    return (tm != 0.f) ? p * ec : 0.5f;            // 0.5 = half-scaled exp(0)
}

// fused: even blocks -> softmax weights; odd blocks -> emb transpose
__global__ void __launch_bounds__(512) k_prep(const float* __restrict__ times,
                                              const float* __restrict__ type_emb,
                                              const int* __restrict__ real_len) {
    int tid = threadIdx.x;                          // 512
    if (blockIdx.x & 1) {
        // ---------------- emb: [b][d][n] fp16, 64 n per block ----------------
        int idx = (int)blockIdx.x >> 1;             // 0..1023
        int b = idx >> 6;
        int n0 = (idx & 63) * 64;
        int tIdx = n0 >> 11;
        int rl = real_len[tIdx * B_SZ + b];
        int K = (rl + 63) & ~63;
        if ((n0 & 2047) >= K) return;
        int lane = tid & 31;
        int half = (tid >> 5) & 1;                  // which 32-of-64
        int wslot = tid >> 6;                       // 0..7
        int n = n0 + half * 32 + lane;
        float tm = times[(size_t)tIdx * (B_SZ * L_SZ) + (size_t)b * L_SZ + (n & 2047)];
        bool nz = (tm != 0.f);
        uint32_t base = (uint32_t)b * (D_EMBD * N_EV) + n;
        #pragma unroll 4
        for (int ii = 0; ii < 32; ii++) {
            int i = wslot + ii * 8;                 // pair index 0..255
            float x = tm * g_omf[i];
            float r = reduce_f32(x);
            float s, c; __sincosf(r, &s, &c);
            float2 te = *(const float2*)&type_emb[tIdx * D_EMBD + 2 * i];
            __half h0 = __float2half_rn(nz ? s + te.x : 0.f);
            __half h1 = __float2half_rn(nz ? c + te.y : 0.f);
            g_e[base + (uint32_t)(2 * i) * N_EV]     = h0;
            g_e[base + (uint32_t)(2 * i + 1) * N_EV] = h1;
        }
        return;
    }
    // ---------------- weights over valid ranges only ----------------
    extern __shared__ float smW[];
    uint2* tab = (uint2*)smW;                       // TAB_N uint2 (32KB)
    float* ts  = smW + 2 * TAB_N;                   // N_EV floats (16KB)
    int bx = (int)blockIdx.x >> 1;                  // 0..1023
    int b = bx >> 6;
    int gx = bx & 63;
    int rl0 = real_len[b], rl1 = real_len[B_SZ + b];
    int K0 = (rl0 + 63) & ~63, K1 = (rl1 + 63) & ~63;
    for (int j = tid; j < TAB_N; j += 512) tab[j] = g_tabh[j];
    for (int j = tid; j < K0; j += 512)
        ts[j] = times[(size_t)b * L_SZ + j];
    for (int j = tid; j < K1; j += 512)
        ts[2048 + j] = times[(size_t)(B_SZ * L_SZ) + (size_t)b * L_SZ + j];
    __syncthreads();
    int warp = tid >> 5, lane = tid & 31;
    int g = gx * 16 + warp;
    float ec0 = g_ec[g], ec1 = g_ec[G_SZ + g];
    float mg = (float)g + 0.5f;
    uint32_t base = ((uint32_t)(b * G_SZ + g)) << 12;

    // pass A: min distance among valid nonzero events (registers only)
    float umin0 = 1e9f, umin1 = 1e9f;
    for (int n0 = lane * 4; n0 < K0; n0 += 128) {
        float4 t4 = *(const float4*)&ts[n0];
        #pragma unroll
        for (int q = 0; q < 4; q++) {
            float tm = (q == 0) ? t4.x : (q == 1) ? t4.y : (q == 2) ? t4.z : t4.w;
            bool valid = (n0 + q < rl0) && (tm != 0.f);
            umin0 = fminf(umin0, valid ? fabsf(tm - mg) : 1e9f);
        }
    }
    for (int n0 = lane * 4; n0 < K1; n0 += 128) {
        float4 t4 = *(const float4*)&ts[2048 + n0];
        #pragma unroll
        for (int q = 0; q < 4; q++) {
            float tm = (q == 0) ? t4.x : (q == 1) ? t4.y : (q == 2) ? t4.z : t4.w;
            bool valid = (n0 + q < rl1) && (tm != 0.f);
            umin1 = fminf(umin1, valid ? fabsf(tm - mg) : 1e9f);
        }
    }
    #pragma unroll
    for (int off = 16; off; off >>= 1) {
        umin0 = fminf(umin0, __shfl_xor_sync(0xffffffffu, umin0, off));
        umin1 = fminf(umin1, __shfl_xor_sync(0xffffffffu, umin1, off));
    }
    float b0 = w_rawh(tab, mg + fminf(umin0, 1023.5f), mg, ec0);
    float b1 = w_rawh(tab, mg + fminf(umin1, 1023.5f), mg, ec1);
    float bound = fmaxf(fmaxf(b0, b1), 0.5f);
    float invb = 1.0f / bound;

    // pass B: interp + quantize + fp32 sum of quantized values
    float sum = 0.f;
    #pragma unroll 1
    for (int seg = 0; seg < 2; seg++) {
        int K  = seg ? K1 : K0;
        int rl = seg ? rl1 : rl0;
        float ec = seg ? ec1 : ec0;
        int off_ts = seg ? 2048 : 0;
        for (int n0 = lane * 4; n0 < K; n0 += 128) {
            float4 t4 = *(const float4*)&ts[off_ts + n0];
            float w[4];
            #pragma unroll
            for (int q = 0; q < 4; q++) {
                float tm = (q == 0) ? t4.x : (q == 1) ? t4.y : (q == 2) ? t4.z : t4.w;
                float wr = w_rawh(tab, tm, mg, ec);
                w[q] = (n0 + q < rl) ? wr * invb : 0.f;
            }
            __half2 p0 = __floats2half2_rn(w[0], w[1]);
            __half2 p1 = __floats2half2_rn(w[2], w[3]);
            float2 f0 = __half22float2(p0);
            float2 f1 = __half22float2(p1);
            sum += (f0.x + f0.y) + (f1.x + f1.y);
            uint2 pk = make_uint2(*(uint32_t*)&p0, *(uint32_t*)&p1);
            *(uint2*)&g_w[base + off_ts + n0] = pk;
        }
    }
    #pragma unroll
    for (int off = 16; off; off >>= 1) sum += __shfl_xor_sync(0xffffffffu, sum, off);
    if (lane == 0) g_sc[b * G_SZ + g] = 1.0f / sum;
}

// ---------------- fp16 mma.sync GEMM: ragged K, 128x128 tiles (R12 config) ----------------
#define KT 64
#define STAGES 3
#define A_TILE_B (128 * 128)           // 16384 (128 rows x 128B)
#define STG_B (2 * A_TILE_B)           // 32768

__global__ void __launch_bounds__(256, 2) k_gemm(const int* __restrict__ real_len,
                                                 float* __restrict__ out) {
    extern __shared__ char smG[];
    uint32_t smb = smem_u32(smG);
    float* smInv = (float*)(smG + STAGES * STG_B);
    int tid = threadIdx.x, wid = tid >> 5, lane = tid & 31;
    int b  = blockIdx.x;                      // b fastest -> waves mix all b's
    int g0 = (blockIdx.y & 7) * 128;
    int d0 = (blockIdx.y >> 3) * 128;
    int wm = wid >> 2, wn = wid & 3;          // 2 x 4 warps; warp tile 64g x 32d

    int nk0 = (((real_len[b] + 63) & ~63) >> 6);
    int nk1 = (((real_len[B_SZ + b] + 63) & ~63) >> 6);
    int nk  = nk0 + nk1;                      // 2..64

    if (tid < 128) smInv[tid] = g_sc[b * G_SZ + g0 + tid];

    const __half* wbase = g_w + (((uint32_t)(b * G_SZ + g0)) << 12);
    const __half* ebase = g_e + (((uint32_t)(b * D_EMBD + d0)) << 12);

    auto kof = [&](int i) { return i < nk0 ? i * KT : (i - nk0) * KT + 2048; };

    auto load_stage = [&](int s, int k0) {
        uint32_t st = smb + s * STG_B;
        #pragma unroll
        for (int t = 0; t < 4; t++) {           // A: 128 rows x 8 chunks
            int id = tid + t * 256;
            int row = id >> 3, c = id & 7;
            uint32_t col = (uint32_t)(c * 16) ^ (uint32_t)((row & 7) << 4);
            cp16(st + row * 128 + col, wbase + ((uint32_t)row << 12) + k0 + c * 8);
        }
        #pragma unroll
        for (int t = 0; t < 4; t++) {           // B: 128 rows x 8 chunks
            int id = tid + t * 256;
            int row = id >> 3, c = id & 7;
            uint32_t col = (uint32_t)(c * 16) ^ (uint32_t)((row & 7) << 4);
            cp16(st + A_TILE_B + row * 128 + col, ebase + ((uint32_t)row << 12) + k0 + c * 8);
        }
        asm volatile("cp.async.commit_group;" ::: "memory");
    };

    float acc[4][4][4];
    #pragma unroll
    for (int i = 0; i < 4; i++)
        #pragma unroll
        for (int j = 0; j < 4; j++)
            #pragma unroll
            for (int q = 0; q < 4; q++) acc[i][j][q] = 0.f;

    load_stage(0, kof(0));
    load_stage(1, kof(1));

    int a_row = (lane & 7) + ((lane >> 3) & 1) * 8;
    int a_col = (lane >> 4) * 16;
    int b_grp = lane >> 3;
    int b_row = (b_grp >> 1) * 8 + (lane & 7);
    int b_col = (b_grp & 1) * 16;
    uint32_t lxor = (uint32_t)((lane & 7) << 4);

    for (int i = 0; i < nk; i++) {
        if (i < nk - 1) asm volatile("cp.async.wait_group 1;" ::: "memory");
        else            asm volatile("cp.async.wait_group 0;" ::: "memory");
        __syncthreads();

        int s = i % 3;
        uint32_t abase = smb + s * STG_B;
        uint32_t bbase = abase + A_TILE_B;
        #pragma unroll
        for (int ks = 0; ks < 4; ks++) {
            uint32_t acol = ((uint32_t)(ks * 32 + a_col)) ^ lxor;
            uint32_t bcol = ((uint32_t)(ks * 32 + b_col)) ^ lxor;
            uint32_t af[4][4], bf[2][4];
            #pragma unroll
            for (int m = 0; m < 4; m++)
                ldm_x4(af[m], abase + (wm * 64 + m * 16 + a_row) * 128 + acol);
            #pragma unroll
            for (int jp = 0; jp < 2; jp++)
                ldm_x4(bf[jp], bbase + (wn * 32 + jp * 16 + b_row) * 128 + bcol);
            #pragma unroll
            for (int m = 0; m < 4; m++)
                #pragma unroll
                for (int j = 0; j < 4; j++)
                    mma16816(acc[m][j], af[m], bf[j >> 1][(j & 1) * 2], bf[j >> 1][(j & 1) * 2 + 1]);
        }
        if (i + 2 < nk) load_stage((i + 2) % 3, kof(i + 2));
    }

    #pragma unroll
    for (int m = 0; m < 4; m++) {
        int r0 = wm * 64 + m * 16 + (lane >> 2);
        float sc0 = smInv[r0], sc1 = smInv[r0 + 8];
        uint32_t gr0 = (uint32_t)(b * G_SZ + g0 + r0) * D_EMBD + d0 + wn * 32;
        #pragma unroll
        for (int j = 0; j < 4; j++) {
            int col = j * 8 + (lane & 3) * 2;
            *(float2*)(out + gr0 + col) =
                make_float2(acc[m][j][0] * sc0, acc[m][j][1] * sc0);
            *(float2*)(out + gr0 + 8 * D_EMBD + col) =
                make_float2(acc[m][j][2] * sc1, acc[m][j][3] * sc1);
        }
    }
}

// ---------------- launch ----------------
extern "C" void kernel_launch(void* const* d_in, const int* in_sizes, int n_in,
                              void* d_out, int out_size) {
    const float* times    = (const float*)d_in[0];
    const float* type_emb = (const float*)d_in[1];
    const int*   real_len = (const int*)d_in[2];
    float* out = (float*)d_out;
    (void)in_sizes; (void)n_in; (void)out_size;

    size_t smem_w = (size_t)(2 * TAB_N + N_EV) * sizeof(float);              // 48 KB
    size_t smem_g = STAGES * STG_B + 128 * sizeof(float);                    // ~96.5 KB
    cudaFuncSetAttribute(k_prep, cudaFuncAttributeMaxDynamicSharedMemorySize, (int)smem_w);
    cudaFuncSetAttribute(k_gemm, cudaFuncAttributeMaxDynamicSharedMemorySize, (int)smem_g);

    k_setup<<<768, 256>>>(type_emb);
    k_prep<<<2048, 512, smem_w>>>(times, type_emb, real_len);
    k_gemm<<<dim3(B_SZ, (G_SZ / 128) * (D_EMBD / 128)), 256, smem_g>>>(real_len, out);
}

// round 15
// speedup vs baseline: 1.0821x; 1.0539x over previous
#include <cuda_runtime.h>
#include <cuda_fp16.h>
#include <math.h>
#include <stdint.h>

#define T_TYPES 2
#define B_SZ 16
#define L_SZ 2048
#define N_EV 4096          // T*L
#define D_EMBD 512
#define G_SZ 1024
#define NPAIR 256          // D/2
#define TAB_N 4096         // symmetric table, u in [0,1024], h = 1/4
#define INV_SQRT_D 0.04419417382415922f
#define LOG2_1E4_OVER_256 0.051905126482615036f   // log2(10000)/256

// ---------------- device scratch ----------------
__device__ float  g_omf[NPAIR];
__device__ uint2  g_tabh[TAB_N];                     // half4 cubic coeffs (c0,c1,c2,c3)
__device__ float  g_ec[T_TYPES * G_SZ];              // exp(type_emb . q[g] / sqrt(D))
__device__ float  g_sc[B_SZ * G_SZ];                 // 1 / sum(stored w)
__device__ __align__(128) __half g_w[(size_t)B_SZ * G_SZ * N_EV];   // 128MB
__device__ __align__(128) __half g_e[(size_t)B_SZ * D_EMBD * N_EV]; // 64MB

// ---------------- helpers ----------------
__device__ __forceinline__ uint32_t smem_u32(const void* p) {
    uint32_t a;
    asm("{ .reg .u64 t; cvta.to.shared.u64 t, %1; cvt.u32.u64 %0, t; }" : "=r"(a) : "l"(p));
    return a;
}
__device__ __forceinline__ void cp16(uint32_t dst, const void* src) {
    asm volatile("cp.async.cg.shared.global [%0], [%1], 16;" :: "r"(dst), "l"(src));
}
__device__ __forceinline__ void ldm_x4(uint32_t (&r)[4], uint32_t addr) {
    asm volatile("ldmatrix.sync.aligned.m8n8.x4.shared.b16 {%0,%1,%2,%3}, [%4];"
                 : "=r"(r[0]), "=r"(r[1]), "=r"(r[2]), "=r"(r[3]) : "r"(addr));
}
__device__ __forceinline__ void mma16816(float (&c)[4], const uint32_t (&a)[4],
                                         uint32_t b0, uint32_t b1) {
    asm volatile("mma.sync.aligned.m16n8k16.row.col.f32.f16.f16.f32 "
                 "{%0,%1,%2,%3}, {%4,%5,%6,%7}, {%8,%9}, {%0,%1,%2,%3};"
                 : "+f"(c[0]), "+f"(c[1]), "+f"(c[2]), "+f"(c[3])
                 : "r"(a[0]), "r"(a[1]), "r"(a[2]), "r"(a[3]), "r"(b0), "r"(b1));
}
// fp32 Cody-Waite range reduction: x in [0, 1024], |r| <= pi
__device__ __forceinline__ float reduce_f32(float x) {
    const float INV2PI = 0.15915494309189535f;
    const float C1 = 6.28125f;
    const float C2 = 1.9353071795864769e-3f;
    float kf = rintf(x * INV2PI);
    float r = fmaf(-kf, C1, x);
    return fmaf(-kf, C2, r);
}

// ---------------- setup: baked table + ec in ONE launch ----------------
__global__ void k_setup(const float* __restrict__ type_emb) {
    int lane = threadIdx.x & 31;
    if (blockIdx.x < 512) {
        if (blockIdx.x == 0 && threadIdx.x < NPAIR)
            g_omf[threadIdx.x] = exp2f(-(float)threadIdx.x * LOG2_1E4_OVER_256);
        int j = (blockIdx.x * blockDim.x + threadIdx.x) >> 5;   // 0..4095
        float u0 = (float)j * 0.25f;
        float u1 = u0 + 0.25f;
        float rc0 = 0.f, rs0 = 0.f, rc1 = 0.f, rs1 = 0.f;
        #pragma unroll
        for (int q = 0; q < 8; q++) {
            int i = lane + q * 32;
            float om = exp2f(-(float)i * LOG2_1E4_OVER_256);
            float s, c;
            __sincosf(reduce_f32(u0 * om), &s, &c);
            rc0 += c; rs0 += om * s;
            __sincosf(reduce_f32(u1 * om), &s, &c);
            rc1 += c; rs1 += om * s;
        }
        #pragma unroll
        for (int off = 16; off; off >>= 1) {
            rc0 += __shfl_xor_sync(0xffffffffu, rc0, off);
            rs0 += __shfl_xor_sync(0xffffffffu, rs0, off);
            rc1 += __shfl_xor_sync(0xffffffffu, rc1, off);
            rs1 += __shfl_xor_sync(0xffffffffu, rs1, off);
        }
        if (lane == 0) {
            float H0  = expf(rc0 * INV_SQRT_D) * 0.5f;           // prescale 1/2
            float Hd0 = -H0 * rs0 * INV_SQRT_D * 0.25f;          // (H/2)' * h
            float H1  = expf(rc1 * INV_SQRT_D) * 0.5f;
            float Hd1 = -H1 * rs1 * INV_SQRT_D * 0.25f;
            float d  = H1 - H0;
            float c2 = 3.f * d - 2.f * Hd0 - Hd1;
            float c3 = Hd0 + Hd1 - 2.f * d;
            __half2 lo = __floats2half2_rn(H0, Hd0);
            __half2 hi = __floats2half2_rn(c2, c3);
            g_tabh[j] = make_uint2(*(uint32_t*)&lo, *(uint32_t*)&hi);
        }
    } else {
        int e = (((int)blockIdx.x - 512) * 256 + threadIdx.x) >> 5;   // 0..2047
        int t = e >> 10, g = e & 1023;
        float mg = (float)g + 0.5f;
        float acc = 0.f;
        #pragma unroll
        for (int q = 0; q < 8; q++) {
            int i = lane + q * 32;
            float om = exp2f(-(float)i * LOG2_1E4_OVER_256);
            float r = reduce_f32(mg * om);
            float s, c; __sincosf(r, &s, &c);
            acc += type_emb[t * D_EMBD + 2 * i] * s + type_emb[t * D_EMBD + 2 * i + 1] * c;
        }
        #pragma unroll
        for (int off = 16; off; off >>= 1) acc += __shfl_xor_sync(0xffffffffu, acc, off);
        if (lane == 0) g_ec[t * G_SZ + g] = expf(acc * INV_SQRT_D);
    }
}

// half-scaled H interp: pre-baked cubic coeffs, 3-FMA Horner (returns H/2)
__device__ __forceinline__ float h_interp(const uint2* tab, float u) {
    float x  = u * 4.f;
    float xf = floorf(x);
    int idx  = (int)xf;
    float fr = x - xf;
    uint2 T = tab[idx];
    float2 a = __half22float2(*(__half2*)&T.x);    // (c0, c1)
    float2 b = __half22float2(*(__half2*)&T.y);    // (c2, c3)
    return fmaf(fr, fmaf(fr, fmaf(fr, b.y, b.x), a.y), a.x);
}

// fused: even blocks -> softmax weights (FIXED 1/64 scale, no bound pass);
//        odd blocks  -> emb transpose
__global__ void __launch_bounds__(512) k_prep(const float* __restrict__ times,
                                              const float* __restrict__ type_emb,
                                              const int* __restrict__ real_len) {
    int tid = threadIdx.x;                          // 512
    if (blockIdx.x & 1) {
        // ---------------- emb: [b][d][n] fp16, 64 n per block ----------------
        int idx = (int)blockIdx.x >> 1;             // 0..1023
        int b = idx >> 6;
        int n0 = (idx & 63) * 64;
        int tIdx = n0 >> 11;
        int rl = real_len[tIdx * B_SZ + b];
        int K = (rl + 63) & ~63;
        if ((n0 & 2047) >= K) return;
        int lane = tid & 31;
        int half = (tid >> 5) & 1;                  // which 32-of-64
        int wslot = tid >> 6;                       // 0..7
        int n = n0 + half * 32 + lane;
        float tm = times[(size_t)tIdx * (B_SZ * L_SZ) + (size_t)b * L_SZ + (n & 2047)];
        bool nz = (tm != 0.f);
        uint32_t base = (uint32_t)b * (D_EMBD * N_EV) + n;
        #pragma unroll 4
        for (int ii = 0; ii < 32; ii++) {
            int i = wslot + ii * 8;                 // pair index 0..255
            float x = tm * g_omf[i];
            float r = reduce_f32(x);
            float s, c; __sincosf(r, &s, &c);
            float2 te = *(const float2*)&type_emb[tIdx * D_EMBD + 2 * i];
            __half h0 = __float2half_rn(nz ? s + te.x : 0.f);
            __half h1 = __float2half_rn(nz ? c + te.y : 0.f);
            g_e[base + (uint32_t)(2 * i) * N_EV]     = h0;
            g_e[base + (uint32_t)(2 * i + 1) * N_EV] = h1;
        }
        return;
    }
    // ---------------- weights over valid ranges only ----------------
    extern __shared__ float smW[];
    uint2* tab = (uint2*)smW;                       // TAB_N uint2 (32KB)
    float* ts  = smW + 2 * TAB_N;                   // N_EV floats (16KB)
    int bx = (int)blockIdx.x >> 1;                  // 0..1023
    int b = bx >> 6;
    int gx = bx & 63;
    int rl0 = real_len[b], rl1 = real_len[B_SZ + b];
    int K0 = (rl0 + 63) & ~63, K1 = (rl1 + 63) & ~63;
    for (int j = tid; j < TAB_N; j += 512) tab[j] = g_tabh[j];
    for (int j = tid; j < K0; j += 512)
        ts[j] = times[(size_t)b * L_SZ + j];
    for (int j = tid; j < K1; j += 512)
        ts[2048 + j] = times[(size_t)(B_SZ * L_SZ) + (size_t)b * L_SZ + j];
    __syncthreads();
    int warp = tid >> 5, lane = tid & 31;
    int g = gx * 16 + warp;
    // eci = ec / 32; stored weight = (H/2) * eci = H*ec/64  (fixed 1/64 scale)
    float eci0 = g_ec[g] * 0.03125f, eci1 = g_ec[G_SZ + g] * 0.03125f;
    float mg = (float)g + 0.5f;
    uint32_t base = ((uint32_t)(b * G_SZ + g)) << 12;

    // single pass: interp + quantize + fp32 sum
    float sum = 0.f;
    #pragma unroll 1
    for (int seg = 0; seg < 2; seg++) {
        int K  = seg ? K1 : K0;
        int rl = seg ? rl1 : rl0;
        float eci = seg ? eci1 : eci0;
        int off_ts = seg ? 2048 : 0;
        for (int n0 = lane * 4; n0 < K; n0 += 128) {
            float4 t4 = *(const float4*)&ts[off_ts + n0];
            float w[4];
            #pragma unroll
            for (int q = 0; q < 4; q++) {
                float tm = (q == 0) ? t4.x : (q == 1) ? t4.y : (q == 2) ? t4.z : t4.w;
                float p = h_interp(tab, fabsf(tm - mg));
                float wr = (tm != 0.f) ? p * eci : 0.015625f;   // exp(0)/64
                w[q] = (n0 + q < rl) ? wr : 0.f;
                sum += w[q];
            }
            __half2 p0 = __floats2half2_rn(w[0], w[1]);
            __half2 p1 = __floats2half2_rn(w[2], w[3]);
            uint2 pk = make_uint2(*(uint32_t*)&p0, *(uint32_t*)&p1);
            *(uint2*)&g_w[base + off_ts + n0] = pk;
        }
    }
    #pragma unroll
    for (int off = 16; off; off >>= 1) sum += __shfl_xor_sync(0xffffffffu, sum, off);
    if (lane == 0) g_sc[b * G_SZ + g] = 1.0f / sum;
}

// ---------------- fp16 mma.sync GEMM: ragged K, 128x128 tiles (R12 config) ----------------
#define KT 64
#define STAGES 3
#define A_TILE_B (128 * 128)           // 16384 (128 rows x 128B)
#define STG_B (2 * A_TILE_B)           // 32768

__global__ void __launch_bounds__(256, 2) k_gemm(const int* __restrict__ real_len,
                                                 float* __restrict__ out) {
    extern __shared__ char smG[];
    uint32_t smb = smem_u32(smG);
    float* smInv = (float*)(smG + STAGES * STG_B);
    int tid = threadIdx.x, wid = tid >> 5, lane = tid & 31;
    int b  = blockIdx.x;                      // b fastest -> waves mix all b's
    int g0 = (blockIdx.y & 7) * 128;
    int d0 = (blockIdx.y >> 3) * 128;
    int wm = wid >> 2, wn = wid & 3;          // 2 x 4 warps; warp tile 64g x 32d

    int nk0 = (((real_len[b] + 63) & ~63) >> 6);
    int nk1 = (((real_len[B_SZ + b] + 63) & ~63) >> 6);
    int nk  = nk0 + nk1;                      // 2..64

    if (tid < 128) smInv[tid] = g_sc[b * G_SZ + g0 + tid];

    const __half* wbase = g_w + (((uint32_t)(b * G_SZ + g0)) << 12);
    const __half* ebase = g_e + (((uint32_t)(b * D_EMBD + d0)) << 12);

    auto kof = [&](int i) { return i < nk0 ? i * KT : (i - nk0) * KT + 2048; };

    auto load_stage = [&](int s, int k0) {
        uint32_t st = smb + s * STG_B;
        #pragma unroll
        for (int t = 0; t < 4; t++) {           // A: 128 rows x 8 chunks
            int id = tid + t * 256;
            int row = id >> 3, c = id & 7;
            uint32_t col = (uint32_t)(c * 16) ^ (uint32_t)((row & 7) << 4);
            cp16(st + row * 128 + col, wbase + ((uint32_t)row << 12) + k0 + c * 8);
        }
        #pragma unroll
        for (int t = 0; t < 4; t++) {           // B: 128 rows x 8 chunks
            int id = tid + t * 256;
            int row = id >> 3, c = id & 7;
            uint32_t col = (uint32_t)(c * 16) ^ (uint32_t)((row & 7) << 4);
            cp16(st + A_TILE_B + row * 128 + col, ebase + ((uint32_t)row << 12) + k0 + c * 8);
        }
        asm volatile("cp.async.commit_group;" ::: "memory");
    };

    float acc[4][4][4];
    #pragma unroll
    for (int i = 0; i < 4; i++)
        #pragma unroll
        for (int j = 0; j < 4; j++)
            #pragma unroll
            for (int q = 0; q < 4; q++) acc[i][j][q] = 0.f;

    load_stage(0, kof(0));
    load_stage(1, kof(1));

    int a_row = (lane & 7) + ((lane >> 3) & 1) * 8;
    int a_col = (lane >> 4) * 16;
    int b_grp = lane >> 3;
    int b_row = (b_grp >> 1) * 8 + (lane & 7);
    int b_col = (b_grp & 1) * 16;
    uint32_t lxor = (uint32_t)((lane & 7) << 4);

    for (int i = 0; i < nk; i++) {
        if (i < nk - 1) asm volatile("cp.async.wait_group 1;" ::: "memory");
        else            asm volatile("cp.async.wait_group 0;" ::: "memory");
        __syncthreads();

        int s = i % 3;
        uint32_t abase = smb + s * STG_B;
        uint32_t bbase = abase + A_TILE_B;
        #pragma unroll
        for (int ks = 0; ks < 4; ks++) {
            uint32_t acol = ((uint32_t)(ks * 32 + a_col)) ^ lxor;
            uint32_t bcol = ((uint32_t)(ks * 32 + b_col)) ^ lxor;
            uint32_t af[4][4], bf[2][4];
            #pragma unroll
            for (int m = 0; m < 4; m++)
                ldm_x4(af[m], abase + (wm * 64 + m * 16 + a_row) * 128 + acol);
            #pragma unroll
            for (int jp = 0; jp < 2; jp++)
                ldm_x4(bf[jp], bbase + (wn * 32 + jp * 16 + b_row) * 128 + bcol);
            #pragma unroll
            for (int m = 0; m < 4; m++)
                #pragma unroll
                for (int j = 0; j < 4; j++)
                    mma16816(acc[m][j], af[m], bf[j >> 1][(j & 1) * 2], bf[j >> 1][(j & 1) * 2 + 1]);
        }
        if (i + 2 < nk) load_stage((i + 2) % 3, kof(i + 2));
    }

    #pragma unroll
    for (int m = 0; m < 4; m++) {
        int r0 = wm * 64 + m * 16 + (lane >> 2);
        float sc0 = smInv[r0], sc1 = smInv[r0 + 8];
        uint32_t gr0 = (uint32_t)(b * G_SZ + g0 + r0) * D_EMBD + d0 + wn * 32;
        #pragma unroll
        for (int j = 0; j < 4; j++) {
            int col = j * 8 + (lane & 3) * 2;
            *(float2*)(out + gr0 + col) =
                make_float2(acc[m][j][0] * sc0, acc[m][j][1] * sc0);
            *(float2*)(out + gr0 + 8 * D_EMBD + col) =
                make_float2(acc[m][j][2] * sc1, acc[m][j][3] * sc1);
        }
    }
}

// ---------------- launch ----------------
extern "C" void kernel_launch(void* const* d_in, const int* in_sizes, int n_in,
                              void* d_out, int out_size) {
    const float* times    = (const float*)d_in[0];
    const float* type_emb = (const float*)d_in[1];
    const int*   real_len = (const int*)d_in[2];
    float* out = (float*)d_out;
    (void)in_sizes; (void)n_in; (void)out_size;

    size_t smem_w = (size_t)(2 * TAB_N + N_EV) * sizeof(float);              // 48 KB
    size_t smem_g = STAGES * STG_B + 128 * sizeof(float);                    // ~96.5 KB
    cudaFuncSetAttribute(k_prep, cudaFuncAttributeMaxDynamicSharedMemorySize, (int)smem_w);
    cudaFuncSetAttribute(k_gemm, cudaFuncAttributeMaxDynamicSharedMemorySize, (int)smem_g);

    k_setup<<<768, 256>>>(type_emb);
    k_prep<<<2048, 512, smem_w>>>(times, type_emb, real_len);
    k_gemm<<<dim3(B_SZ, (G_SZ / 128) * (D_EMBD / 128)), 256, smem_g>>>(real_len, out);
}

// round 16
// speedup vs baseline: 1.2760x; 1.1792x over previous
#include <cuda_runtime.h>
#include <cuda_fp16.h>
#include <math.h>
#include <stdint.h>

#define T_TYPES 2
#define B_SZ 16
#define L_SZ 2048
#define N_EV 4096          // T*L
#define D_EMBD 512
#define G_SZ 1024
#define NPAIR 256          // D/2
#define TAB_N 4096         // symmetric table, u in [0,1024], h = 1/4
#define INV_SQRT_D 0.04419417382415922f
#define LOG2_1E4_OVER_256 0.051905126482615036f   // log2(10000)/256

// ---------------- device scratch ----------------
__device__ float  g_omf[NPAIR];
__device__ uint2  g_tabh[TAB_N];                     // half4 cubic coeffs (c0,c1,c2,c3)
__device__ float  g_ec[T_TYPES * G_SZ];              // exp(type_emb . q[g] / sqrt(D))
__device__ float  g_sc[B_SZ * G_SZ];                 // 1 / sum(stored w)
__device__ int    g_bord[B_SZ];                      // b order, descending nk (LPT)
__device__ __align__(128) __half g_w[(size_t)B_SZ * G_SZ * N_EV];   // 128MB
__device__ __align__(128) __half g_e[(size_t)B_SZ * D_EMBD * N_EV]; // 64MB

// ---------------- helpers ----------------
__device__ __forceinline__ uint32_t smem_u32(const void* p) {
    uint32_t a;
    asm("{ .reg .u64 t; cvta.to.shared.u64 t, %1; cvt.u32.u64 %0, t; }" : "=r"(a) : "l"(p));
    return a;
}
__device__ __forceinline__ void cp16(uint32_t dst, const void* src) {
    asm volatile("cp.async.cg.shared.global [%0], [%1], 16;" :: "r"(dst), "l"(src));
}
__device__ __forceinline__ void ldm_x4(uint32_t (&r)[4], uint32_t addr) {
    asm volatile("ldmatrix.sync.aligned.m8n8.x4.shared.b16 {%0,%1,%2,%3}, [%4];"
                 : "=r"(r[0]), "=r"(r[1]), "=r"(r[2]), "=r"(r[3]) : "r"(addr));
}
__device__ __forceinline__ void mma16816(float (&c)[4], const uint32_t (&a)[4],
                                         uint32_t b0, uint32_t b1) {
    asm volatile("mma.sync.aligned.m16n8k16.row.col.f32.f16.f16.f32 "
                 "{%0,%1,%2,%3}, {%4,%5,%6,%7}, {%8,%9}, {%0,%1,%2,%3};"
                 : "+f"(c[0]), "+f"(c[1]), "+f"(c[2]), "+f"(c[3])
                 : "r"(a[0]), "r"(a[1]), "r"(a[2]), "r"(a[3]), "r"(b0), "r"(b1));
}
// fp32 Cody-Waite range reduction: x in [0, 1024], |r| <= pi
__device__ __forceinline__ float reduce_f32(float x) {
    const float INV2PI = 0.15915494309189535f;
    const float C1 = 6.28125f;
    const float C2 = 1.9353071795864769e-3f;
    float kf = rintf(x * INV2PI);
    float r = fmaf(-kf, C1, x);
    return fmaf(-kf, C2, r);
}

// ---------------- setup: baked table + ec + LPT order in ONE launch ----------------
__global__ void k_setup(const float* __restrict__ type_emb,
                        const int* __restrict__ real_len) {
    int lane = threadIdx.x & 31;
    if (blockIdx.x < 512) {
        if (blockIdx.x == 0 && threadIdx.x < NPAIR)
            g_omf[threadIdx.x] = exp2f(-(float)threadIdx.x * LOG2_1E4_OVER_256);
        int j = (blockIdx.x * blockDim.x + threadIdx.x) >> 5;   // 0..4095
        float u0 = (float)j * 0.25f;
        float u1 = u0 + 0.25f;
        float rc0 = 0.f, rs0 = 0.f, rc1 = 0.f, rs1 = 0.f;
        #pragma unroll
        for (int q = 0; q < 8; q++) {
            int i = lane + q * 32;
            float om = exp2f(-(float)i * LOG2_1E4_OVER_256);
            float s, c;
            __sincosf(reduce_f32(u0 * om), &s, &c);
            rc0 += c; rs0 += om * s;
            __sincosf(reduce_f32(u1 * om), &s, &c);
            rc1 += c; rs1 += om * s;
        }
        #pragma unroll
        for (int off = 16; off; off >>= 1) {
            rc0 += __shfl_xor_sync(0xffffffffu, rc0, off);
            rs0 += __shfl_xor_sync(0xffffffffu, rs0, off);
            rc1 += __shfl_xor_sync(0xffffffffu, rc1, off);
            rs1 += __shfl_xor_sync(0xffffffffu, rs1, off);
        }
        if (lane == 0) {
            float H0  = expf(rc0 * INV_SQRT_D) * 0.5f;           // prescale 1/2
            float Hd0 = -H0 * rs0 * INV_SQRT_D * 0.25f;          // (H/2)' * h
            float H1  = expf(rc1 * INV_SQRT_D) * 0.5f;
            float Hd1 = -H1 * rs1 * INV_SQRT_D * 0.25f;
            float d  = H1 - H0;
            float c2 = 3.f * d - 2.f * Hd0 - Hd1;
            float c3 = Hd0 + Hd1 - 2.f * d;
            __half2 lo = __floats2half2_rn(H0, Hd0);
            __half2 hi = __floats2half2_rn(c2, c3);
            g_tabh[j] = make_uint2(*(uint32_t*)&lo, *(uint32_t*)&hi);
        }
    } else if (blockIdx.x < 768) {
        int e = (((int)blockIdx.x - 512) * 256 + threadIdx.x) >> 5;   // 0..2047
        int t = e >> 10, g = e & 1023;
        float mg = (float)g + 0.5f;
        float acc = 0.f;
        #pragma unroll
        for (int q = 0; q < 8; q++) {
            int i = lane + q * 32;
            float om = exp2f(-(float)i * LOG2_1E4_OVER_256);
            float r = reduce_f32(mg * om);
            float s, c; __sincosf(r, &s, &c);
            acc += type_emb[t * D_EMBD + 2 * i] * s + type_emb[t * D_EMBD + 2 * i + 1] * c;
        }
        #pragma unroll
        for (int off = 16; off; off >>= 1) acc += __shfl_xor_sync(0xffffffffu, acc, off);
        if (lane == 0) g_ec[t * G_SZ + g] = expf(acc * INV_SQRT_D);
    } else if (threadIdx.x == 0) {
        // LPT order: sort b by descending total k-tiles
        int nk[B_SZ], ord[B_SZ];
        #pragma unroll
        for (int b = 0; b < B_SZ; b++) {
            nk[b] = (((real_len[b] + 63) & ~63) >> 6) +
                    (((real_len[B_SZ + b] + 63) & ~63) >> 6);
            ord[b] = b;
        }
        #pragma unroll
        for (int i = 0; i < B_SZ - 1; i++)
            #pragma unroll
            for (int j = 0; j < B_SZ - 1 - i; j++)
                if (nk[j] < nk[j + 1]) {
                    int t0 = nk[j]; nk[j] = nk[j + 1]; nk[j + 1] = t0;
                    int t1 = ord[j]; ord[j] = ord[j + 1]; ord[j + 1] = t1;
                }
        #pragma unroll
        for (int b = 0; b < B_SZ; b++) g_bord[b] = ord[b];
    }
}

// half-scaled H interp: pre-baked cubic coeffs, 3-FMA Horner (returns H/2)
__device__ __forceinline__ float h_interp(const uint2* tab, float u) {
    float x  = u * 4.f;
    float xf = floorf(x);
    int idx  = (int)xf;
    float fr = x - xf;
    uint2 T = tab[idx];
    float2 a = __half22float2(*(__half2*)&T.x);    // (c0, c1)
    float2 b = __half22float2(*(__half2*)&T.y);    // (c2, c3)
    return fmaf(fr, fmaf(fr, fmaf(fr, b.y, b.x), a.y), a.x);
}

// fused: even blocks -> softmax weights (FIXED 1/64 scale); odd -> emb transpose
__global__ void __launch_bounds__(512) k_prep(const float* __restrict__ times,
                                              const float* __restrict__ type_emb,
                                              const int* __restrict__ real_len) {
    int tid = threadIdx.x;                          // 512
    if (blockIdx.x & 1) {
        // ---------------- emb: [b][d][n] fp16, 64 n per block ----------------
        int idx = (int)blockIdx.x >> 1;             // 0..1023
        int b = idx >> 6;
        int n0 = (idx & 63) * 64;
        int tIdx = n0 >> 11;
        int rl = real_len[tIdx * B_SZ + b];
        int K = (rl + 63) & ~63;
        if ((n0 & 2047) >= K) return;
        int lane = tid & 31;
        int half = (tid >> 5) & 1;                  // which 32-of-64
        int wslot = tid >> 6;                       // 0..7
        int n = n0 + half * 32 + lane;
        float tm = times[(size_t)tIdx * (B_SZ * L_SZ) + (size_t)b * L_SZ + (n & 2047)];
        bool nz = (tm != 0.f);
        uint32_t base = (uint32_t)b * (D_EMBD * N_EV) + n;
        #pragma unroll 4
        for (int ii = 0; ii < 32; ii++) {
            int i = wslot + ii * 8;                 // pair index 0..255
            float x = tm * g_omf[i];
            float r = reduce_f32(x);
            float s, c; __sincosf(r, &s, &c);
            float2 te = *(const float2*)&type_emb[tIdx * D_EMBD + 2 * i];
            __half h0 = __float2half_rn(nz ? s + te.x : 0.f);
            __half h1 = __float2half_rn(nz ? c + te.y : 0.f);
            g_e[base + (uint32_t)(2 * i) * N_EV]     = h0;
            g_e[base + (uint32_t)(2 * i + 1) * N_EV] = h1;
        }
        return;
    }
    // ---------------- weights over valid ranges only ----------------
    extern __shared__ float smW[];
    uint2* tab = (uint2*)smW;                       // TAB_N uint2 (32KB)
    float* ts  = smW + 2 * TAB_N;                   // N_EV floats (16KB)
    int bx = (int)blockIdx.x >> 1;                  // 0..1023
    int b = bx >> 6;
    int gx = bx & 63;
    int rl0 = real_len[b], rl1 = real_len[B_SZ + b];
    int K0 = (rl0 + 63) & ~63, K1 = (rl1 + 63) & ~63;
    for (int j = tid; j < TAB_N; j += 512) tab[j] = g_tabh[j];
    for (int j = tid; j < K0; j += 512)
        ts[j] = times[(size_t)b * L_SZ + j];
    for (int j = tid; j < K1; j += 512)
        ts[2048 + j] = times[(size_t)(B_SZ * L_SZ) + (size_t)b * L_SZ + j];
    __syncthreads();
    int warp = tid >> 5, lane = tid & 31;
    int g = gx * 16 + warp;
    float eci0 = g_ec[g] * 0.03125f, eci1 = g_ec[G_SZ + g] * 0.03125f;
    float mg = (float)g + 0.5f;
    uint32_t base = ((uint32_t)(b * G_SZ + g)) << 12;

    float sum = 0.f;
    #pragma unroll 1
    for (int seg = 0; seg < 2; seg++) {
        int K  = seg ? K1 : K0;
        int rl = seg ? rl1 : rl0;
        float eci = seg ? eci1 : eci0;
        int off_ts = seg ? 2048 : 0;
        for (int n0 = lane * 4; n0 < K; n0 += 128) {
            float4 t4 = *(const float4*)&ts[off_ts + n0];
            float w[4];
            #pragma unroll
            for (int q = 0; q < 4; q++) {
                float tm = (q == 0) ? t4.x : (q == 1) ? t4.y : (q == 2) ? t4.z : t4.w;
                float p = h_interp(tab, fabsf(tm - mg));
                float wr = (tm != 0.f) ? p * eci : 0.015625f;   // exp(0)/64
                w[q] = (n0 + q < rl) ? wr : 0.f;
                sum += w[q];
            }
            __half2 p0 = __floats2half2_rn(w[0], w[1]);
            __half2 p1 = __floats2half2_rn(w[2], w[3]);
            uint2 pk = make_uint2(*(uint32_t*)&p0, *(uint32_t*)&p1);
            *(uint2*)&g_w[base + off_ts + n0] = pk;
        }
    }
    #pragma unroll
    for (int off = 16; off; off >>= 1) sum += __shfl_xor_sync(0xffffffffu, sum, off);
    if (lane == 0) g_sc[b * G_SZ + g] = 1.0f / sum;
}

// ---------------- fp16 mma.sync GEMM: ragged K, 128x128 tiles, LPT order ----------------
#define KT 64
#define STAGES 3
#define A_TILE_B (128 * 128)           // 16384 (128 rows x 128B)
#define STG_B (2 * A_TILE_B)           // 32768

__global__ void __launch_bounds__(256, 2) k_gemm(const int* __restrict__ real_len,
                                                 float* __restrict__ out) {
    extern __shared__ char smG[];
    uint32_t smb = smem_u32(smG);
    float* smInv = (float*)(smG + STAGES * STG_B);
    int tid = threadIdx.x, wid = tid >> 5, lane = tid & 31;
    // LPT: 32 consecutive CTAs = all tiles of one b, biggest-nk b first
    int b  = g_bord[blockIdx.x >> 5];
    int t  = blockIdx.x & 31;
    int g0 = (t & 7) * 128;                    // g0 fastest: 8 CTAs share e-tile (b,d0)
    int d0 = (t >> 3) * 128;
    int wm = wid >> 2, wn = wid & 3;           // 2 x 4 warps; warp tile 64g x 32d

    int nk0 = (((real_len[b] + 63) & ~63) >> 6);
    int nk1 = (((real_len[B_SZ + b] + 63) & ~63) >> 6);
    int nk  = nk0 + nk1;                       // 2..64

    if (tid < 128) smInv[tid] = g_sc[b * G_SZ + g0 + tid];

    const __half* wbase = g_w + (((uint32_t)(b * G_SZ + g0)) << 12);
    const __half* ebase = g_e + (((uint32_t)(b * D_EMBD + d0)) << 12);

    auto kof = [&](int i) { return i < nk0 ? i * KT : (i - nk0) * KT + 2048; };

    auto load_stage = [&](int s, int k0) {
        uint32_t st = smb + s * STG_B;
        #pragma unroll
        for (int t2 = 0; t2 < 4; t2++) {        // A: 128 rows x 8 chunks
            int id = tid + t2 * 256;
            int row = id >> 3, c = id & 7;
            uint32_t col = (uint32_t)(c * 16) ^ (uint32_t)((row & 7) << 4);
            cp16(st + row * 128 + col, wbase + ((uint32_t)row << 12) + k0 + c * 8);
        }
        #pragma unroll
        for (int t2 = 0; t2 < 4; t2++) {        // B: 128 rows x 8 chunks
            int id = tid + t2 * 256;
            int row = id >> 3, c = id & 7;
            uint32_t col = (uint32_t)(c * 16) ^ (uint32_t)((row & 7) << 4);
            cp16(st + A_TILE_B + row * 128 + col, ebase + ((uint32_t)row << 12) + k0 + c * 8);
        }
        asm volatile("cp.async.commit_group;" ::: "memory");
    };

    float acc[4][4][4];
    #pragma unroll
    for (int i = 0; i < 4; i++)
        #pragma unroll
        for (int j = 0; j < 4; j++)
            #pragma unroll
            for (int q = 0; q < 4; q++) acc[i][j][q] = 0.f;

    load_stage(0, kof(0));
    load_stage(1, kof(1));

    int a_row = (lane & 7) + ((lane >> 3) & 1) * 8;
    int a_col = (lane >> 4) * 16;
    int b_grp = lane >> 3;
    int b_row = (b_grp >> 1) * 8 + (lane & 7);
    int b_col = (b_grp & 1) * 16;
    uint32_t lxor = (uint32_t)((lane & 7) << 4);

    for (int i = 0; i < nk; i++) {
        if (i < nk - 1) asm volatile("cp.async.wait_group 1;" ::: "memory");
        else            asm volatile("cp.async.wait_group 0;" ::: "memory");
        __syncthreads();

        int s = i % 3;
        uint32_t abase = smb + s * STG_B;
        uint32_t bbase = abase + A_TILE_B;
        #pragma unroll
        for (int ks = 0; ks < 4; ks++) {
            uint32_t acol = ((uint32_t)(ks * 32 + a_col)) ^ lxor;
            uint32_t bcol = ((uint32_t)(ks * 32 + b_col)) ^ lxor;
            uint32_t af[4][4], bf[2][4];
            #pragma unroll
            for (int m = 0; m < 4; m++)
                ldm_x4(af[m], abase + (wm * 64 + m * 16 + a_row) * 128 + acol);
            #pragma unroll
            for (int jp = 0; jp < 2; jp++)
                ldm_x4(bf[jp], bbase + (wn * 32 + jp * 16 + b_row) * 128 + bcol);
            #pragma unroll
            for (int m = 0; m < 4; m++)
                #pragma unroll
                for (int j = 0; j < 4; j++)
                    mma16816(acc[m][j], af[m], bf[j >> 1][(j & 1) * 2], bf[j >> 1][(j & 1) * 2 + 1]);
        }
        if (i + 2 < nk) load_stage((i + 2) % 3, kof(i + 2));
    }

    #pragma unroll
    for (int m = 0; m < 4; m++) {
        int r0 = wm * 64 + m * 16 + (lane >> 2);
        float sc0 = smInv[r0], sc1 = smInv[r0 + 8];
        uint32_t gr0 = (uint32_t)(b * G_SZ + g0 + r0) * D_EMBD + d0 + wn * 32;
        #pragma unroll
        for (int j = 0; j < 4; j++) {
            int col = j * 8 + (lane & 3) * 2;
            *(float2*)(out + gr0 + col) =
                make_float2(acc[m][j][0] * sc0, acc[m][j][1] * sc0);
            *(float2*)(out + gr0 + 8 * D_EMBD + col) =
                make_float2(acc[m][j][2] * sc1, acc[m][j][3] * sc1);
        }
    }
}

// ---------------- launch ----------------
extern "C" void kernel_launch(void* const* d_in, const int* in_sizes, int n_in,
                              void* d_out, int out_size) {
    const float* times    = (const float*)d_in[0];
    const float* type_emb = (const float*)d_in[1];
    const int*   real_len = (const int*)d_in[2];
    float* out = (float*)d_out;
    (void)in_sizes; (void)n_in; (void)out_size;

    size_t smem_w = (size_t)(2 * TAB_N + N_EV) * sizeof(float);              // 48 KB
    size_t smem_g = STAGES * STG_B + 128 * sizeof(float);                    // ~96.5 KB
    cudaFuncSetAttribute(k_prep, cudaFuncAttributeMaxDynamicSharedMemorySize, (int)smem_w);
    cudaFuncSetAttribute(k_gemm, cudaFuncAttributeMaxDynamicSharedMemorySize, (int)smem_g);

    k_setup<<<769, 256>>>(type_emb, real_len);
    k_prep<<<2048, 512, smem_w>>>(times, type_emb, real_len);
    k_gemm<<<512, 256, smem_g>>>(real_len, out);
}

// round 17
// speedup vs baseline: 1.2763x; 1.0002x over previous
#include <cuda_runtime.h>
#include <cuda_fp16.h>
#include <math.h>
#include <stdint.h>

#define T_TYPES 2
#define B_SZ 16
#define L_SZ 2048
#define N_EV 4096          // T*L
#define D_EMBD 512
#define G_SZ 1024
#define NPAIR 256          // D/2
#define TAB_N 4096         // symmetric table, u in [0,1024], h = 1/4
#define INV_SQRT_D 0.04419417382415922f
#define LOG2_1E4_OVER_256 0.051905126482615036f   // log2(10000)/256

// ---------------- device scratch ----------------
__device__ float  g_omf[NPAIR];
__device__ uint2  g_tabh[TAB_N];                     // half4 cubic coeffs (c0,c1,c2,c3)
__device__ float  g_ec[T_TYPES * G_SZ];              // exp(type_emb . q[g] / sqrt(D))
__device__ float  g_sc[B_SZ * G_SZ];                 // 1 / sum(stored w)
__device__ int    g_bord[B_SZ];                      // b order, descending nk (LPT)
__device__ __align__(128) __half g_w[(size_t)B_SZ * G_SZ * N_EV];   // 128MB
__device__ __align__(128) __half g_e[(size_t)B_SZ * D_EMBD * N_EV]; // 64MB

// ---------------- helpers ----------------
__device__ __forceinline__ uint32_t smem_u32(const void* p) {
    uint32_t a;
    asm("{ .reg .u64 t; cvta.to.shared.u64 t, %1; cvt.u32.u64 %0, t; }" : "=r"(a) : "l"(p));
    return a;
}
__device__ __forceinline__ void cp16(uint32_t dst, const void* src) {
    asm volatile("cp.async.cg.shared.global [%0], [%1], 16;" :: "r"(dst), "l"(src));
}
__device__ __forceinline__ void ldm_x4(uint32_t (&r)[4], uint32_t addr) {
    asm volatile("ldmatrix.sync.aligned.m8n8.x4.shared.b16 {%0,%1,%2,%3}, [%4];"
                 : "=r"(r[0]), "=r"(r[1]), "=r"(r[2]), "=r"(r[3]) : "r"(addr));
}
__device__ __forceinline__ void mma16816(float (&c)[4], const uint32_t (&a)[4],
                                         uint32_t b0, uint32_t b1) {
    asm volatile("mma.sync.aligned.m16n8k16.row.col.f32.f16.f16.f32 "
                 "{%0,%1,%2,%3}, {%4,%5,%6,%7}, {%8,%9}, {%0,%1,%2,%3};"
                 : "+f"(c[0]), "+f"(c[1]), "+f"(c[2]), "+f"(c[3])
                 : "r"(a[0]), "r"(a[1]), "r"(a[2]), "r"(a[3]), "r"(b0), "r"(b1));
}
// fp32 Cody-Waite range reduction: x in [0, 1024], |r| <= pi
__device__ __forceinline__ float reduce_f32(float x) {
    const float INV2PI = 0.15915494309189535f;
    const float C1 = 6.28125f;
    const float C2 = 1.9353071795864769e-3f;
    float kf = rintf(x * INV2PI);
    float r = fmaf(-kf, C1, x);
    return fmaf(-kf, C2, r);
}

// ---------------- setup: baked table + ec + LPT order in ONE launch ----------------
__global__ void k_setup(const float* __restrict__ type_emb,
                        const int* __restrict__ real_len) {
    int lane = threadIdx.x & 31;
    if (blockIdx.x < 512) {
        if (blockIdx.x == 0 && threadIdx.x < NPAIR)
            g_omf[threadIdx.x] = exp2f(-(float)threadIdx.x * LOG2_1E4_OVER_256);
        int j = (blockIdx.x * blockDim.x + threadIdx.x) >> 5;   // 0..4095
        float u0 = (float)j * 0.25f;
        float u1 = u0 + 0.25f;
        float rc0 = 0.f, rs0 = 0.f, rc1 = 0.f, rs1 = 0.f;
        #pragma unroll
        for (int q = 0; q < 8; q++) {
            int i = lane + q * 32;
            float om = exp2f(-(float)i * LOG2_1E4_OVER_256);
            float s, c;
            __sincosf(reduce_f32(u0 * om), &s, &c);
            rc0 += c; rs0 += om * s;
            __sincosf(reduce_f32(u1 * om), &s, &c);
            rc1 += c; rs1 += om * s;
        }
        #pragma unroll
        for (int off = 16; off; off >>= 1) {
            rc0 += __shfl_xor_sync(0xffffffffu, rc0, off);
            rs0 += __shfl_xor_sync(0xffffffffu, rs0, off);
            rc1 += __shfl_xor_sync(0xffffffffu, rc1, off);
            rs1 += __shfl_xor_sync(0xffffffffu, rs1, off);
        }
        if (lane == 0) {
            float H0  = expf(rc0 * INV_SQRT_D) * 0.5f;           // prescale 1/2
            float Hd0 = -H0 * rs0 * INV_SQRT_D * 0.25f;          // (H/2)' * h
            float H1  = expf(rc1 * INV_SQRT_D) * 0.5f;
            float Hd1 = -H1 * rs1 * INV_SQRT_D * 0.25f;
            float d  = H1 - H0;
            float c2 = 3.f * d - 2.f * Hd0 - Hd1;
            float c3 = Hd0 + Hd1 - 2.f * d;
            __half2 lo = __floats2half2_rn(H0, Hd0);
            __half2 hi = __floats2half2_rn(c2, c3);
            g_tabh[j] = make_uint2(*(uint32_t*)&lo, *(uint32_t*)&hi);
        }
    } else if (blockIdx.x < 768) {
        int e = (((int)blockIdx.x - 512) * 256 + threadIdx.x) >> 5;   // 0..2047
        int t = e >> 10, g = e & 1023;
        float mg = (float)g + 0.5f;
        float acc = 0.f;
        #pragma unroll
        for (int q = 0; q < 8; q++) {
            int i = lane + q * 32;
            float om = exp2f(-(float)i * LOG2_1E4_OVER_256);
            float r = reduce_f32(mg * om);
            float s, c; __sincosf(r, &s, &c);
            acc += type_emb[t * D_EMBD + 2 * i] * s + type_emb[t * D_EMBD + 2 * i + 1] * c;
        }
        #pragma unroll
        for (int off = 16; off; off >>= 1) acc += __shfl_xor_sync(0xffffffffu, acc, off);
        if (lane == 0) g_ec[t * G_SZ + g] = expf(acc * INV_SQRT_D);
    } else if (threadIdx.x == 0) {
        // LPT order: sort b by descending total k-tiles
        int nk[B_SZ], ord[B_SZ];
        #pragma unroll
        for (int b = 0; b < B_SZ; b++) {
            nk[b] = (((real_len[b] + 63) & ~63) >> 6) +
                    (((real_len[B_SZ + b] + 63) & ~63) >> 6);
            ord[b] = b;
        }
        #pragma unroll
        for (int i = 0; i < B_SZ - 1; i++)
            #pragma unroll
            for (int j = 0; j < B_SZ - 1 - i; j++)
                if (nk[j] < nk[j + 1]) {
                    int t0 = nk[j]; nk[j] = nk[j + 1]; nk[j + 1] = t0;
                    int t1 = ord[j]; ord[j] = ord[j + 1]; ord[j + 1] = t1;
                }
        #pragma unroll
        for (int b = 0; b < B_SZ; b++) g_bord[b] = ord[b];
    }
}

// half-scaled H interp: pre-baked cubic coeffs, 3-FMA Horner (returns H/2)
__device__ __forceinline__ float h_interp(const uint2* tab, float u) {
    float x  = u * 4.f;
    float xf = floorf(x);
    int idx  = (int)xf;
    float fr = x - xf;
    uint2 T = tab[idx];
    float2 a = __half22float2(*(__half2*)&T.x);    // (c0, c1)
    float2 b = __half22float2(*(__half2*)&T.y);    // (c2, c3)
    return fmaf(fr, fmaf(fr, fmaf(fr, b.y, b.x), a.y), a.x);
}

// fused, LPT-ordered: even blocks -> softmax weights; odd -> emb transpose
__global__ void __launch_bounds__(512) k_prep(const float* __restrict__ times,
                                              const float* __restrict__ type_emb,
                                              const int* __restrict__ real_len) {
    int tid = threadIdx.x;                          // 512
    if (blockIdx.x & 1) {
        // ---------------- emb: [b][d][n] fp16, 64 n per block ----------------
        int idx = (int)blockIdx.x >> 1;             // 0..1023
        int b = g_bord[idx >> 6];                   // LPT order
        int n0 = (idx & 63) * 64;
        int tIdx = n0 >> 11;
        int rl = real_len[tIdx * B_SZ + b];
        int K = (rl + 63) & ~63;
        if ((n0 & 2047) >= K) return;
        int lane = tid & 31;
        int half = (tid >> 5) & 1;                  // which 32-of-64
        int wslot = tid >> 6;                       // 0..7
        int n = n0 + half * 32 + lane;
        float tm = times[(size_t)tIdx * (B_SZ * L_SZ) + (size_t)b * L_SZ + (n & 2047)];
        bool nz = (tm != 0.f);
        uint32_t base = (uint32_t)b * (D_EMBD * N_EV) + n;
        #pragma unroll 4
        for (int ii = 0; ii < 32; ii++) {
            int i = wslot + ii * 8;                 // pair index 0..255
            float x = tm * g_omf[i];
            float r = reduce_f32(x);
            float s, c; __sincosf(r, &s, &c);
            float2 te = *(const float2*)&type_emb[tIdx * D_EMBD + 2 * i];
            __half h0 = __float2half_rn(nz ? s + te.x : 0.f);
            __half h1 = __float2half_rn(nz ? c + te.y : 0.f);
            g_e[base + (uint32_t)(2 * i) * N_EV]     = h0;
            g_e[base + (uint32_t)(2 * i + 1) * N_EV] = h1;
        }
        return;
    }
    // ---------------- weights over valid ranges only ----------------
    extern __shared__ float smW[];
    uint2* tab = (uint2*)smW;                       // TAB_N uint2 (32KB)
    float* ts  = smW + 2 * TAB_N;                   // N_EV floats (16KB)
    int bx = (int)blockIdx.x >> 1;                  // 0..1023
    int b = g_bord[bx >> 6];                        // LPT order
    int gx = bx & 63;
    int rl0 = real_len[b], rl1 = real_len[B_SZ + b];
    int K0 = (rl0 + 63) & ~63, K1 = (rl1 + 63) & ~63;
    for (int j = tid; j < TAB_N; j += 512) tab[j] = g_tabh[j];
    for (int j = tid; j < K0; j += 512)
        ts[j] = times[(size_t)b * L_SZ + j];
    for (int j = tid; j < K1; j += 512)
        ts[2048 + j] = times[(size_t)(B_SZ * L_SZ) + (size_t)b * L_SZ + j];
    __syncthreads();
    int warp = tid >> 5, lane = tid & 31;
    int g = gx * 16 + warp;
    float eci0 = g_ec[g] * 0.03125f, eci1 = g_ec[G_SZ + g] * 0.03125f;
    float mg = (float)g + 0.5f;
    uint32_t base = ((uint32_t)(b * G_SZ + g)) << 12;

    float sum = 0.f;
    #pragma unroll 1
    for (int seg = 0; seg < 2; seg++) {
        int K  = seg ? K1 : K0;
        int rl = seg ? rl1 : rl0;
        float eci = seg ? eci1 : eci0;
        int off_ts = seg ? 2048 : 0;
        for (int n0 = lane * 4; n0 < K; n0 += 128) {
            float4 t4 = *(const float4*)&ts[off_ts + n0];
            float w[4];
            #pragma unroll
            for (int q = 0; q < 4; q++) {
                float tm = (q == 0) ? t4.x : (q == 1) ? t4.y : (q == 2) ? t4.z : t4.w;
                float p = h_interp(tab, fabsf(tm - mg));
                float wr = (tm != 0.f) ? p * eci : 0.015625f;   // exp(0)/64
                w[q] = (n0 + q < rl) ? wr : 0.f;
                sum += w[q];
            }
            __half2 p0 = __floats2half2_rn(w[0], w[1]);
            __half2 p1 = __floats2half2_rn(w[2], w[3]);
            uint2 pk = make_uint2(*(uint32_t*)&p0, *(uint32_t*)&p1);
            *(uint2*)&g_w[base + off_ts + n0] = pk;
        }
    }
    #pragma unroll
    for (int off = 16; off; off >>= 1) sum += __shfl_xor_sync(0xffffffffu, sum, off);
    if (lane == 0) g_sc[b * G_SZ + g] = 1.0f / sum;
}

// ---------------- fp16 mma.sync GEMM: ragged K, 128x128 tiles, LPT order ----------------
#define KT 64
#define STAGES 3
#define A_TILE_B (128 * 128)           // 16384 (128 rows x 128B)
#define STG_B (2 * A_TILE_B)           // 32768

__global__ void __launch_bounds__(256, 2) k_gemm(const int* __restrict__ real_len,
                                                 float* __restrict__ out) {
    extern __shared__ char smG[];
    uint32_t smb = smem_u32(smG);
    float* smInv = (float*)(smG + STAGES * STG_B);
    int tid = threadIdx.x, wid = tid >> 5, lane = tid & 31;
    // LPT: 32 consecutive CTAs = all tiles of one b, biggest-nk b first
    int b  = g_bord[blockIdx.x >> 5];
    int t  = blockIdx.x & 31;
    int g0 = (t & 7) * 128;                    // g0 fastest: 8 CTAs share e-tile (b,d0)
    int d0 = (t >> 3) * 128;
    int wm = wid >> 2, wn = wid & 3;           // 2 x 4 warps; warp tile 64g x 32d

    int nk0 = (((real_len[b] + 63) & ~63) >> 6);
    int nk1 = (((real_len[B_SZ + b] + 63) & ~63) >> 6);
    int nk  = nk0 + nk1;                       // 2..64

    if (tid < 128) smInv[tid] = g_sc[b * G_SZ + g0 + tid];

    const __half* wbase = g_w + (((uint32_t)(b * G_SZ + g0)) << 12);
    const __half* ebase = g_e + (((uint32_t)(b * D_EMBD + d0)) << 12);

    auto kof = [&](int i) { return i < nk0 ? i * KT : (i - nk0) * KT + 2048; };

    auto load_stage = [&](int s, int k0) {
        uint32_t st = smb + s * STG_B;
        #pragma unroll
        for (int t2 = 0; t2 < 4; t2++) {        // A: 128 rows x 8 chunks
            int id = tid + t2 * 256;
            int row = id >> 3, c = id & 7;
            uint32_t col = (uint32_t)(c * 16) ^ (uint32_t)((row & 7) << 4);
            cp16(st + row * 128 + col, wbase + ((uint32_t)row << 12) + k0 + c * 8);
        }
        #pragma unroll
        for (int t2 = 0; t2 < 4; t2++) {        // B: 128 rows x 8 chunks
            int id = tid + t2 * 256;
            int row = id >> 3, c = id & 7;
            uint32_t col = (uint32_t)(c * 16) ^ (uint32_t)((row & 7) << 4);
            cp16(st + A_TILE_B + row * 128 + col, ebase + ((uint32_t)row << 12) + k0 + c * 8);
        }
        asm volatile("cp.async.commit_group;" ::: "memory");
    };

    float acc[4][4][4];
    #pragma unroll
    for (int i = 0; i < 4; i++)
        #pragma unroll
        for (int j = 0; j < 4; j++)
            #pragma unroll
            for (int q = 0; q < 4; q++) acc[i][j][q] = 0.f;

    load_stage(0, kof(0));
    load_stage(1, kof(1));

    int a_row = (lane & 7) + ((lane >> 3) & 1) * 8;
    int a_col = (lane >> 4) * 16;
    int b_grp = lane >> 3;
    int b_row = (b_grp >> 1) * 8 + (lane & 7);
    int b_col = (b_grp & 1) * 16;
    uint32_t lxor = (uint32_t)((lane & 7) << 4);

    for (int i = 0; i < nk; i++) {
        if (i < nk - 1) asm volatile("cp.async.wait_group 1;" ::: "memory");
        else            asm volatile("cp.async.wait_group 0;" ::: "memory");
        __syncthreads();

        int s = i % 3;
        uint32_t abase = smb + s * STG_B;
        uint32_t bbase = abase + A_TILE_B;
        #pragma unroll
        for (int ks = 0; ks < 4; ks++) {
            uint32_t acol = ((uint32_t)(ks * 32 + a_col)) ^ lxor;
            uint32_t bcol = ((uint32_t)(ks * 32 + b_col)) ^ lxor;
            uint32_t af[4][4], bf[2][4];
            #pragma unroll
            for (int m = 0; m < 4; m++)
                ldm_x4(af[m], abase + (wm * 64 + m * 16 + a_row) * 128 + acol);
            #pragma unroll
            for (int jp = 0; jp < 2; jp++)
                ldm_x4(bf[jp], bbase + (wn * 32 + jp * 16 + b_row) * 128 + bcol);
            #pragma unroll
            for (int m = 0; m < 4; m++)
                #pragma unroll
                for (int j = 0; j < 4; j++)
                    mma16816(acc[m][j], af[m], bf[j >> 1][(j & 1) * 2], bf[j >> 1][(j & 1) * 2 + 1]);
        }
        if (i + 2 < nk) load_stage((i + 2) % 3, kof(i + 2));
    }

    #pragma unroll
    for (int m = 0; m < 4; m++) {
        int r0 = wm * 64 + m * 16 + (lane >> 2);
        float sc0 = smInv[r0], sc1 = smInv[r0 + 8];
        uint32_t gr0 = (uint32_t)(b * G_SZ + g0 + r0) * D_EMBD + d0 + wn * 32;
        #pragma unroll
        for (int j = 0; j < 4; j++) {
            int col = j * 8 + (lane & 3) * 2;
            *(float2*)(out + gr0 + col) =
                make_float2(acc[m][j][0] * sc0, acc[m][j][1] * sc0);
            *(float2*)(out + gr0 + 8 * D_EMBD + col) =
                make_float2(acc[m][j][2] * sc1, acc[m][j][3] * sc1);
        }
    }
}

// ---------------- launch ----------------
extern "C" void kernel_launch(void* const* d_in, const int* in_sizes, int n_in,
                              void* d_out, int out_size) {
    const float* times    = (const float*)d_in[0];
    const float* type_emb = (const float*)d_in[1];
    const int*   real_len = (const int*)d_in[2];
    float* out = (float*)d_out;
    (void)in_sizes; (void)n_in; (void)out_size;

    size_t smem_w = (size_t)(2 * TAB_N + N_EV) * sizeof(float);              // 48 KB
    size_t smem_g = STAGES * STG_B + 128 * sizeof(float);                    // ~96.5 KB
    cudaFuncSetAttribute(k_prep, cudaFuncAttributeMaxDynamicSharedMemorySize, (int)smem_w);
    cudaFuncSetAttribute(k_gemm, cudaFuncAttributeMaxDynamicSharedMemorySize, (int)smem_g);

    k_setup<<<769, 256>>>(type_emb, real_len);
    k_prep<<<2048, 512, smem_w>>>(times, type_emb, real_len);
    k_gemm<<<512, 256, smem_g>>>(real_len, out);
}